// round 3
// baseline (speedup 1.0000x reference)
#include <cuda_runtime.h>
#include <cuda_fp16.h>

#define LN_EPS 1e-12f

struct SmemU {
    union {
        struct {                        // embd2 role
            __half tab[130 * 64];       // 16640 B  (LN(W_rel) in half)
            int    sid[2][512];         // 4096 B   (byte offsets, -1 = diag)
            int    stype[512];          // 2048 B
        } e2;
        struct {                        // compute role
            float sx[8][768];           // 24576 B  (pre-LN embd1 rows)
            float sWd[16][65];          // 4160 B   (W_diag k-chunk)
            float wsum[8], wsq[8];
            float stat[2];
        } e1;
    };
};

__global__ void __launch_bounds__(256, 7) k_fused(
    const int* __restrict__ tok, const int* __restrict__ tty,
    const float* __restrict__ Wword, const float* __restrict__ Wtype,
    const float* __restrict__ Wabs,  const float* __restrict__ Wrel,
    const float* __restrict__ Wglob, const float* __restrict__ Wdiag,
    const float* __restrict__ bdiag,
    float* __restrict__ out0, float* __restrict__ out1,
    float* __restrict__ out2) {

    __shared__ SmemU sm;
    const int bid  = blockIdx.x;
    const int t    = threadIdx.x;
    const int warp = t >> 5, lane = t & 31;

    if ((bid % 5) != 4) {
        // ==================== embd2 role: 2048 blocks, 2 rows each =========
        const int eid = bid - bid / 5;
        const int R0  = eid * 2;            // rows R0, R0+1 (same batch)
        const int b   = R0 >> 9;
        const int i0  = R0 & 511;

        // ---- build half LN(W_rel) table: 2 threads per row ----
        {
            int r = t >> 1, h = t & 1;      // rows 0..127
            const float* src = Wrel + r * 64 + h * 32;
            float v[32];
            #pragma unroll
            for (int q = 0; q < 8; q++) {
                float4 f = reinterpret_cast<const float4*>(src)[q];
                v[q*4] = f.x; v[q*4+1] = f.y; v[q*4+2] = f.z; v[q*4+3] = f.w;
            }
            float s = 0.f, q2 = 0.f;
            #pragma unroll
            for (int q = 0; q < 32; q++) { s += v[q]; q2 += v[q] * v[q]; }
            s  += __shfl_xor_sync(0xffffffffu, s,  1);
            q2 += __shfl_xor_sync(0xffffffffu, q2, 1);
            float mean = s * (1.0f / 64.0f);
            float inv  = rsqrtf(q2 * (1.0f / 64.0f) - mean * mean + LN_EPS);
            __half2* dst = reinterpret_cast<__half2*>(&sm.e2.tab[r * 64 + h * 32]);
            #pragma unroll
            for (int q = 0; q < 16; q++)
                dst[q] = __floats2half2_rn((v[2*q] - mean) * inv,
                                           (v[2*q+1] - mean) * inv);
        }
        if (t >= 252) {                     // rows 128,129 by lanes 28..31 of warp 7
            int slot = t - 252;
            int r = 128 + (slot >> 1), h = slot & 1;
            const float* src = Wrel + r * 64 + h * 32;
            float v[32];
            #pragma unroll
            for (int q = 0; q < 8; q++) {
                float4 f = reinterpret_cast<const float4*>(src)[q];
                v[q*4] = f.x; v[q*4+1] = f.y; v[q*4+2] = f.z; v[q*4+3] = f.w;
            }
            float s = 0.f, q2 = 0.f;
            #pragma unroll
            for (int q = 0; q < 32; q++) { s += v[q]; q2 += v[q] * v[q]; }
            s  += __shfl_xor_sync(0xf0000000u, s,  1);
            q2 += __shfl_xor_sync(0xf0000000u, q2, 1);
            float mean = s * (1.0f / 64.0f);
            float inv  = rsqrtf(q2 * (1.0f / 64.0f) - mean * mean + LN_EPS);
            __half2* dst = reinterpret_cast<__half2*>(&sm.e2.tab[r * 64 + h * 32]);
            #pragma unroll
            for (int q = 0; q < 16; q++)
                dst[q] = __floats2half2_rn((v[2*q] - mean) * inv,
                                           (v[2*q+1] - mean) * inv);
        }
        for (int j = t; j < 512; j += 256) sm.e2.stype[j] = tty[b * 512 + j];
        __syncthreads();

        for (int rr = 0; rr < 2; rr++) {
            int i  = i0 + rr;
            int ti = sm.e2.stype[i];
            for (int j = t; j < 512; j += 256) {
                int id;
                if (j == i)                      id = -1;          // diag: skip
                else if (i == 0)                 id = 128;
                else if (j == 0)                 id = 129;
                else if (sm.e2.stype[j] != ti)   id = 64;
                else {
                    int d = i - j;
                    id = (d > 0) ? 128 - min(d, 63) : min(-d, 63);
                }
                sm.e2.sid[rr][j] = (id < 0) ? -1 : (id << 7);      // byte offset
            }
        }
        __syncthreads();

        const char* tb = reinterpret_cast<const char*>(sm.e2.tab);
        float4* outp = reinterpret_cast<float4*>(out2) + (size_t)R0 * (512 * 16);
        #pragma unroll 4
        for (int e = t; e < 2 * 512 * 16; e += 256) {
            int j  = (e >> 4) & 511;
            int rr = e >> 13;
            int d4 = e & 15;
            int s  = sm.e2.sid[rr][j];
            if (s >= 0) {
                uint2 hv = *reinterpret_cast<const uint2*>(tb + s + (d4 << 3));
                float2 f0 = __half22float2(*reinterpret_cast<__half2*>(&hv.x));
                float2 f1 = __half22float2(*reinterpret_cast<__half2*>(&hv.y));
                __stcs(&outp[e], make_float4(f0.x, f0.y, f1.x, f1.y));
            }
        }
        return;
    }

    // ==================== compute role: 512 blocks, 8 rows each ============
    const int cid  = bid / 5;
    const int row0 = cid * 8;

    // out0 duty: blocks 0..7 LN 8 rows of W_glob each, broadcast x8 batches
    if (cid < 8) {
        int g = cid * 8 + warp;
        float x0 = Wglob[g * 64 + lane];
        float x1 = Wglob[g * 64 + 32 + lane];
        float s = x0 + x1, q = x0 * x0 + x1 * x1;
        #pragma unroll
        for (int o = 16; o; o >>= 1) {
            s += __shfl_xor_sync(0xffffffffu, s, o);
            q += __shfl_xor_sync(0xffffffffu, q, o);
        }
        float mean = s * (1.0f / 64.0f);
        float inv  = rsqrtf(q * (1.0f / 64.0f) - mean * mean + LN_EPS);
        float v0 = (x0 - mean) * inv, v1 = (x1 - mean) * inv;
        #pragma unroll
        for (int bb = 0; bb < 8; bb++) {
            out0[(bb * 64 + g) * 64 + lane]      = v0;
            out0[(bb * 64 + g) * 64 + 32 + lane] = v1;
        }
    }

    // ---- phase 1: gather + LN embd1 (8 rows) ----
    for (int r = 0; r < 8; r++) {
        int row = row0 + r;
        int s   = row & 511;
        int tk  = tok[row], ty = tty[row];
        const float* pw = Wword + (size_t)tk * 768;
        const float* pt = Wtype + (size_t)ty * 768;
        const float* pa = Wabs  + (size_t)s  * 768;
        float v0 = pw[t      ] + pt[t      ] + pa[t      ];
        float v1 = pw[t + 256] + pt[t + 256] + pa[t + 256];
        float v2 = pw[t + 512] + pt[t + 512] + pa[t + 512];
        sm.e1.sx[r][t] = v0; sm.e1.sx[r][t + 256] = v1; sm.e1.sx[r][t + 512] = v2;

        float s1 = v0 + v1 + v2;
        float q1 = v0 * v0 + v1 * v1 + v2 * v2;
        #pragma unroll
        for (int o = 16; o; o >>= 1) {
            s1 += __shfl_down_sync(0xffffffffu, s1, o);
            q1 += __shfl_down_sync(0xffffffffu, q1, o);
        }
        if (lane == 0) { sm.e1.wsum[warp] = s1; sm.e1.wsq[warp] = q1; }
        __syncthreads();
        if (t == 0) {
            float S = 0.f, Q = 0.f;
            #pragma unroll
            for (int w = 0; w < 8; w++) { S += sm.e1.wsum[w]; Q += sm.e1.wsq[w]; }
            float mean = S * (1.0f / 768.0f);
            float var  = Q * (1.0f / 768.0f) - mean * mean;
            sm.e1.stat[0] = mean; sm.e1.stat[1] = rsqrtf(var + LN_EPS);
        }
        __syncthreads();
        float mean = sm.e1.stat[0], inv = sm.e1.stat[1];
        float* o = out1 + (size_t)row * 768;
        o[t      ] = (v0 - mean) * inv;
        o[t + 256] = (v1 - mean) * inv;
        o[t + 512] = (v2 - mean) * inv;
        __syncthreads();
    }

    // ---- phase 2: diag GEMV, warp-per-row (2 accumulators) ----
    float acc0 = 0.f, acc1 = 0.f;
    for (int c = 0; c < 48; c++) {
        __syncthreads();
        for (int e = t; e < 16 * 64; e += 256) {
            int k = e & 15, d = e >> 4;
            sm.e1.sWd[k][d] = Wdiag[(size_t)d * 768 + c * 16 + k];
        }
        __syncthreads();
        #pragma unroll
        for (int kk = 0; kk < 16; kk++) {
            float xv = sm.e1.sx[warp][c * 16 + kk];
            acc0 += xv * sm.e1.sWd[kk][lane];
            acc1 += xv * sm.e1.sWd[kk][lane + 32];
        }
    }

    {
        float y0 = acc0 + Wrel[lane]      + bdiag[lane];
        float y1 = acc1 + Wrel[lane + 32] + bdiag[lane + 32];
        float S = y0 + y1, Q = y0 * y0 + y1 * y1;
        #pragma unroll
        for (int o = 16; o; o >>= 1) {
            S += __shfl_xor_sync(0xffffffffu, S, o);
            Q += __shfl_xor_sync(0xffffffffu, Q, o);
        }
        float mean = S * (1.0f / 64.0f);
        float inv  = rsqrtf(Q * (1.0f / 64.0f) - mean * mean + LN_EPS);
        int row = row0 + warp;
        int s   = row & 511;
        float* od = out2 + ((size_t)row * 512 + s) * 64;
        od[lane]      = (y0 - mean) * inv;
        od[lane + 32] = (y1 - mean) * inv;
    }
}

// ---------------------------------------------------------------------------
extern "C" void kernel_launch(void* const* d_in, const int* in_sizes, int n_in,
                              void* d_out, int out_size) {
    const int*   tok   = (const int*)d_in[0];
    const int*   tty   = (const int*)d_in[1];
    const float* Wword = (const float*)d_in[2];
    const float* Wtype = (const float*)d_in[3];
    const float* Wabs  = (const float*)d_in[4];
    const float* Wrel  = (const float*)d_in[5];
    const float* Wglob = (const float*)d_in[6];
    const float* Wdiag = (const float*)d_in[7];
    const float* bdiag = (const float*)d_in[8];

    float* out  = (float*)d_out;
    float* out0 = out;                      // [8,64,64]
    float* out1 = out0 + 8 * 64 * 64;       // [8,512,768]
    float* out2 = out1 + 8 * 512 * 768;     // [8,512,512,64]

    k_fused<<<2560, 256>>>(tok, tty, Wword, Wtype, Wabs, Wrel, Wglob, Wdiag,
                           bdiag, out0, out1, out2);
}

// round 4
// speedup vs baseline: 1.2929x; 1.2929x over previous
#include <cuda_runtime.h>

#define LN_EPS 1e-12f

struct SmemU {
    union {
        struct {                        // embd2 role
            float tab[130 * 64];        // 33280 B  LN(W_rel) fp32
            int   sid[4][512];          // 8192 B   float4 row offsets, -1 = diag
            int   stype[512];           // 2048 B
        } e2;
        struct {                        // compute role
            float sx[8][768];           // 24576 B  pre-LN embd1 rows
            float sWd[64][65];          // 16640 B  W_diag chunk [d][k]
            float wsum[8], wsq[8];
            float stat[2];
        } e1;
    };
};

__device__ __forceinline__ void ln_row_pair(const float* __restrict__ src,
                                            float* __restrict__ dstrow,
                                            unsigned mask) {
    // two threads per 64-float row; this thread handles 32 floats at dstrow.
    const float4* s4 = reinterpret_cast<const float4*>(src);
    float4* d4 = reinterpret_cast<float4*>(dstrow);
    float s = 0.f, q = 0.f;
    #pragma unroll
    for (int p = 0; p < 8; p++) {
        float4 f = s4[p];
        d4[p] = f;                       // raw stash
        s += f.x + f.y + f.z + f.w;
        q += f.x*f.x + f.y*f.y + f.z*f.z + f.w*f.w;
    }
    s += __shfl_xor_sync(mask, s, 1);
    q += __shfl_xor_sync(mask, q, 1);
    float mean = s * (1.0f / 64.0f);
    float inv  = rsqrtf(q * (1.0f / 64.0f) - mean * mean + LN_EPS);
    #pragma unroll
    for (int p = 0; p < 8; p++) {
        float4 f = d4[p];
        d4[p] = make_float4((f.x - mean) * inv, (f.y - mean) * inv,
                            (f.z - mean) * inv, (f.w - mean) * inv);
    }
}

__global__ void __launch_bounds__(256, 5) k_fused(
    const int* __restrict__ tok, const int* __restrict__ tty,
    const float* __restrict__ Wword, const float* __restrict__ Wtype,
    const float* __restrict__ Wabs,  const float* __restrict__ Wrel,
    const float* __restrict__ Wglob, const float* __restrict__ Wdiag,
    const float* __restrict__ bdiag,
    float* __restrict__ out0, float* __restrict__ out1,
    float* __restrict__ out2) {

    __shared__ SmemU sm;
    const int bid  = blockIdx.x;
    const int t    = threadIdx.x;
    const int warp = t >> 5, lane = t & 31;

    if ((bid % 3) != 2) {
        // ============ embd2 role: 1024 blocks, 4 rows (one i-panel) each ====
        const int eid = (bid / 3) * 2 + (bid % 3);   // 0..1023
        const int R0  = eid * 4;                     // rows R0..R0+3, same batch
        const int b   = R0 >> 9;
        const int i0  = R0 & 511;

        // ---- LN(W_rel) table, two threads per row, spill-free two-pass ----
        {
            int r = t >> 1, h = t & 1;               // rows 0..127
            ln_row_pair(Wrel + r * 64 + h * 32,
                        &sm.e2.tab[r * 64 + h * 32], 0xffffffffu);
        }
        if ((t & 255) >= 224 && t < 228) {           // lanes 0..3 of warp 7: rows 128,129
            int slot = t - 224;
            int r = 128 + (slot >> 1), h = slot & 1;
            ln_row_pair(Wrel + r * 64 + h * 32,
                        &sm.e2.tab[r * 64 + h * 32], 0x0000000Fu);
        }
        for (int j = t; j < 512; j += 256) sm.e2.stype[j] = tty[b * 512 + j];
        __syncthreads();

        #pragma unroll
        for (int rr = 0; rr < 4; rr++) {
            int i  = i0 + rr;
            int ti = sm.e2.stype[i];
            for (int j = t; j < 512; j += 256) {
                int id;
                if (j == i)                      id = -1;      // diag: skip
                else if (i == 0)                 id = 128;
                else if (j == 0)                 id = 129;
                else if (sm.e2.stype[j] != ti)   id = 64;
                else {
                    int d = i - j;
                    id = (d > 0) ? 128 - min(d, 63) : min(-d, 63);
                }
                sm.e2.sid[rr][j] = (id < 0) ? -1 : (id << 4);  // float4 offset
            }
        }
        __syncthreads();

        const float4* tb4 = reinterpret_cast<const float4*>(sm.e2.tab);
        float4* outp = reinterpret_cast<float4*>(out2) + (size_t)R0 * (512 * 16);
        const int* sidp = &sm.e2.sid[0][0];
        #pragma unroll 4
        for (int e = t; e < 4 * 512 * 16; e += 256) {
            int jr = e >> 4;                  // rr*512 + j
            int d4 = e & 15;
            int s  = sidp[jr];
            if (s >= 0) __stcs(&outp[e], tb4[s + d4]);
        }
        return;
    }

    // ============ compute role: 512 blocks, 8 rows each =====================
    const int cid  = bid / 3;
    const int row0 = cid * 8;

    // out0 duty: blocks 0..7 LN 8 rows of W_glob each, broadcast x8 batches
    if (cid < 8) {
        int g = cid * 8 + warp;
        float x0 = Wglob[g * 64 + lane];
        float x1 = Wglob[g * 64 + 32 + lane];
        float s = x0 + x1, q = x0 * x0 + x1 * x1;
        #pragma unroll
        for (int o = 16; o; o >>= 1) {
            s += __shfl_xor_sync(0xffffffffu, s, o);
            q += __shfl_xor_sync(0xffffffffu, q, o);
        }
        float mean = s * (1.0f / 64.0f);
        float inv  = rsqrtf(q * (1.0f / 64.0f) - mean * mean + LN_EPS);
        float v0 = (x0 - mean) * inv, v1 = (x1 - mean) * inv;
        #pragma unroll
        for (int bb = 0; bb < 8; bb++) {
            out0[(bb * 64 + g) * 64 + lane]      = v0;
            out0[(bb * 64 + g) * 64 + 32 + lane] = v1;
        }
    }

    // ---- phase 1: gather + LN embd1 (8 rows) ----
    for (int r = 0; r < 8; r++) {
        int row = row0 + r;
        int s   = row & 511;
        int tk  = tok[row], ty = tty[row];
        const float* pw = Wword + (size_t)tk * 768;
        const float* pt = Wtype + (size_t)ty * 768;
        const float* pa = Wabs  + (size_t)s  * 768;
        float v0 = pw[t      ] + pt[t      ] + pa[t      ];
        float v1 = pw[t + 256] + pt[t + 256] + pa[t + 256];
        float v2 = pw[t + 512] + pt[t + 512] + pa[t + 512];
        sm.e1.sx[r][t] = v0; sm.e1.sx[r][t + 256] = v1; sm.e1.sx[r][t + 512] = v2;

        float s1 = v0 + v1 + v2;
        float q1 = v0 * v0 + v1 * v1 + v2 * v2;
        #pragma unroll
        for (int o = 16; o; o >>= 1) {
            s1 += __shfl_down_sync(0xffffffffu, s1, o);
            q1 += __shfl_down_sync(0xffffffffu, q1, o);
        }
        if (lane == 0) { sm.e1.wsum[warp] = s1; sm.e1.wsq[warp] = q1; }
        __syncthreads();
        if (t == 0) {
            float S = 0.f, Q = 0.f;
            #pragma unroll
            for (int w = 0; w < 8; w++) { S += sm.e1.wsum[w]; Q += sm.e1.wsq[w]; }
            float mean = S * (1.0f / 768.0f);
            float var  = Q * (1.0f / 768.0f) - mean * mean;
            sm.e1.stat[0] = mean; sm.e1.stat[1] = rsqrtf(var + LN_EPS);
        }
        __syncthreads();
        float mean = sm.e1.stat[0], inv = sm.e1.stat[1];
        float* o = out1 + (size_t)row * 768;
        __stcs(&o[t      ], (v0 - mean) * inv);
        __stcs(&o[t + 256], (v1 - mean) * inv);
        __stcs(&o[t + 512], (v2 - mean) * inv);
        __syncthreads();
    }

    // ---- phase 2: diag GEMV, warp-per-row, 64-k chunks, [d][k] layout ----
    float acc0 = 0.f, acc1 = 0.f;
    for (int c = 0; c < 12; c++) {
        __syncthreads();
        for (int e = t; e < 64 * 64; e += 256) {
            int d = e >> 6, k = e & 63;
            sm.e1.sWd[d][k] = Wdiag[(size_t)d * 768 + c * 64 + k];
        }
        __syncthreads();
        #pragma unroll 16
        for (int kk = 0; kk < 64; kk++) {
            float xv = sm.e1.sx[warp][c * 64 + kk];
            acc0 += xv * sm.e1.sWd[lane][kk];
            acc1 += xv * sm.e1.sWd[lane + 32][kk];
        }
    }

    {
        float y0 = acc0 + Wrel[lane]      + bdiag[lane];
        float y1 = acc1 + Wrel[lane + 32] + bdiag[lane + 32];
        float S = y0 + y1, Q = y0 * y0 + y1 * y1;
        #pragma unroll
        for (int o = 16; o; o >>= 1) {
            S += __shfl_xor_sync(0xffffffffu, S, o);
            Q += __shfl_xor_sync(0xffffffffu, Q, o);
        }
        float mean = S * (1.0f / 64.0f);
        float inv  = rsqrtf(Q * (1.0f / 64.0f) - mean * mean + LN_EPS);
        int row = row0 + warp;
        int s   = row & 511;
        float* od = out2 + ((size_t)row * 512 + s) * 64;
        od[lane]      = (y0 - mean) * inv;
        od[lane + 32] = (y1 - mean) * inv;
    }
}

// ---------------------------------------------------------------------------
extern "C" void kernel_launch(void* const* d_in, const int* in_sizes, int n_in,
                              void* d_out, int out_size) {
    const int*   tok   = (const int*)d_in[0];
    const int*   tty   = (const int*)d_in[1];
    const float* Wword = (const float*)d_in[2];
    const float* Wtype = (const float*)d_in[3];
    const float* Wabs  = (const float*)d_in[4];
    const float* Wrel  = (const float*)d_in[5];
    const float* Wglob = (const float*)d_in[6];
    const float* Wdiag = (const float*)d_in[7];
    const float* bdiag = (const float*)d_in[8];

    float* out  = (float*)d_out;
    float* out0 = out;                      // [8,64,64]
    float* out1 = out0 + 8 * 64 * 64;       // [8,512,768]
    float* out2 = out1 + 8 * 512 * 768;     // [8,512,512,64]

    k_fused<<<1536, 256>>>(tok, tty, Wword, Wtype, Wabs, Wrel, Wglob, Wdiag,
                           bdiag, out0, out1, out2);
}